// round 7
// baseline (speedup 1.0000x reference)
#include <cuda_runtime.h>
#include <cuda_bf16.h>
#include <cstdint>

#define NUSR 100000
#define NITM 50000
#define NNODE (NUSR + NITM)
#define DD 128
#define EE 1500000
#define HALFD 64
#define KCAT 320
#define NBLK 586   // ceil(NNODE/256)

#define SBPAD16 20
#define SBPAD32 36

// interleaved weight buffer offsets (floats): per 8-k group: 4*264 floats
#define DOFF_U  0
#define DOFF_I  42240
#define DOFF_W0 84480
#define DOFF_W1 118272
#define DOFF_V0 152064
#define DOFF_V1 168960
#define DTOT    185856

// -------- scratch (device globals: allocation-free) --------
__device__ float g_bufA[(size_t)NNODE * DD];
__device__ float g_bufB[(size_t)NNODE * DD];
__device__ float g_cat [(size_t)NNODE * KCAT];
__device__ float g_wts [DTOT];
__device__ int   g_deg[NNODE];
__device__ int   g_bsum[1024];
__device__ int   g_offs[NNODE + 1];
__device__ int   g_cursor[NNODE];
__device__ int   g_csr[EE];
__device__ __nv_bfloat16 g_ufeb[5000 * 128];
__device__ __nv_bfloat16 g_ifeb[8000 * 128];
__device__ __nv_bfloat16 g_web [30000 * 64];

// -------- tf32 helpers --------
__device__ __forceinline__ uint32_t f2tf32(float v) {
    uint32_t r;
    asm("cvt.rna.tf32.f32 %0, %1;" : "=r"(r) : "f"(v));
    return r;
}
__device__ __forceinline__ float rtf(float v) { return __uint_as_float(f2tf32(v)); }

__device__ __forceinline__ void mma_tf32(float* c, const uint32_t* a, const uint32_t* b) {
    asm volatile(
        "mma.sync.aligned.m16n8k8.row.col.f32.tf32.tf32.f32 "
        "{%0,%1,%2,%3}, {%4,%5,%6,%7}, {%8,%9}, {%0,%1,%2,%3};"
        : "+f"(c[0]), "+f"(c[1]), "+f"(c[2]), "+f"(c[3])
        : "r"(a[0]), "r"(a[1]), "r"(a[2]), "r"(a[3]), "r"(b[0]), "r"(b[1]));
}

__device__ __forceinline__ void cp16(void* smem_dst, const void* gsrc, bool pred) {
    uint32_t dst = (uint32_t)__cvta_generic_to_shared(smem_dst);
    int sz = pred ? 16 : 0;
    asm volatile("cp.async.ca.shared.global [%0], [%1], 16, %2;\n"
                 :: "r"(dst), "l"(gsrc), "r"(sz));
}
__device__ __forceinline__ void cp_commit() { asm volatile("cp.async.commit_group;\n"); }
__device__ __forceinline__ void cp_wait0()  { asm volatile("cp.async.wait_group 0;\n"); }
__device__ __forceinline__ void cp_wait2()  { asm volatile("cp.async.wait_group 2;\n"); }
__device__ __forceinline__ void cp_wait1()  { asm volatile("cp.async.wait_group 1;\n"); }
__device__ __forceinline__ void cp_wait3()  { asm volatile("cp.async.wait_group 3;\n"); }

// Hs swizzle: row-major [128][128], phys col = col ^ (4*(row&7))
__device__ __forceinline__ int hsw(int r, int c) { return r * 128 + (c ^ ((r & 7) << 2)); }

// -------- utility kernels --------
__global__ void zero_kernel(uint4* __restrict__ p, int n4) {
    int i = blockIdx.x * blockDim.x + threadIdx.x;
    int st = gridDim.x * blockDim.x;
    for (; i < n4; i += st) p[i] = make_uint4(0, 0, 0, 0);
}

// weights -> tf32-rounded, k-pair-interleaved layout:
// (k,n) -> (k>>3)*1056 + (k&3)*264 + n*2 + ((k>>2)&1)
__global__ void roundw_kernel(const float* __restrict__ uW, const float* __restrict__ iW,
                              const float* __restrict__ w0, const float* __restrict__ w1,
                              const float* __restrict__ v0, const float* __restrict__ v1) {
    int i = blockIdx.x * blockDim.x + threadIdx.x;
    if (i >= 180224) return;
    const float* src; int loc, dbase;
    if      (i < 40960)  { src = uW; loc = i;          dbase = DOFF_U;  }
    else if (i < 81920)  { src = iW; loc = i - 40960;  dbase = DOFF_I;  }
    else if (i < 114688) { src = w0; loc = i - 81920;  dbase = DOFF_W0; }
    else if (i < 147456) { src = w1; loc = i - 114688; dbase = DOFF_W1; }
    else if (i < 163840) { src = v0; loc = i - 147456; dbase = DOFF_V0; }
    else                 { src = v1; loc = i - 163840; dbase = DOFF_V1; }
    int k = loc >> 7, n = loc & 127;
    int off = dbase + (k >> 3) * 1056 + (k & 3) * 264 + n * 2 + ((k >> 2) & 1);
    g_wts[off] = rtf(src[loc]);
}

// embedding tables -> bf16
__global__ void conv_tables(const float* __restrict__ ufe, const float* __restrict__ ife,
                            const float* __restrict__ we) {
    int i = blockIdx.x * blockDim.x + threadIdx.x;
    int st = gridDim.x * blockDim.x;
    for (; i < 3584000; i += st) {
        if      (i < 640000)  g_ufeb[i]           = __float2bfloat16(ufe[i]);
        else if (i < 1664000) g_ifeb[i - 640000]  = __float2bfloat16(ife[i - 640000]);
        else                  g_web [i - 1664000] = __float2bfloat16(we [i - 1664000]);
    }
}

__global__ void deg_kernel(const int* __restrict__ dst) {
    int i = blockIdx.x * blockDim.x + threadIdx.x;
    if (i < EE) atomicAdd(&g_deg[dst[i]], 1);
}

__global__ void scan1_kernel() {
    __shared__ int sm[256];
    int tid = threadIdx.x;
    int i = blockIdx.x * 256 + tid;
    int v = (i < NNODE) ? g_deg[i] : 0;
    sm[tid] = v;
    __syncthreads();
#pragma unroll
    for (int d = 1; d < 256; d <<= 1) {
        int t = (tid >= d) ? sm[tid - d] : 0;
        __syncthreads();
        sm[tid] += t;
        __syncthreads();
    }
    if (i < NNODE) g_offs[i] = sm[tid] - v;
    if (tid == 255) g_bsum[blockIdx.x] = sm[255];
}

__global__ void scan2_kernel() {
    __shared__ int sm[1024];
    int tid = threadIdx.x;
    int v = (tid < NBLK) ? g_bsum[tid] : 0;
    sm[tid] = v;
    __syncthreads();
#pragma unroll
    for (int d = 1; d < 1024; d <<= 1) {
        int t = (tid >= d) ? sm[tid - d] : 0;
        __syncthreads();
        sm[tid] += t;
        __syncthreads();
    }
    g_bsum[tid] = sm[tid] - v;
}

__global__ void scan3_kernel() {
    int i = blockIdx.x * blockDim.x + threadIdx.x;
    if (i < NNODE) {
        int o = g_offs[i] + g_bsum[i >> 8];
        g_offs[i] = o;
        g_cursor[i] = o;
    }
    if (i == 0) g_offs[NNODE] = EE;
}

__global__ void fill_kernel(const int* __restrict__ src, const int* __restrict__ dst) {
    int i = blockIdx.x * blockDim.x + threadIdx.x;
    if (i < EE) {
        int d = dst[i];
        int pos = atomicAdd(&g_cursor[d], 1);
        g_csr[pos] = src[i];
    }
}

// -------- gather aggregation (warp per node), invdeg from CSR offsets --------
__global__ void agg_kernel(const float* __restrict__ x, float* __restrict__ out) {
    int gw   = (blockIdx.x * blockDim.x + threadIdx.x) >> 5;
    int lane = threadIdx.x & 31;
    if (gw >= NNODE) return;
    int off = g_offs[gw];
    int end = g_offs[gw + 1];
    float4 acc = make_float4(0.f, 0.f, 0.f, 0.f);
    for (int j = off; j < end; j++) {
        int s = __ldg(&g_csr[j]);
        float4 v = __ldg((const float4*)(x + (size_t)s * DD) + lane);
        acc.x += v.x; acc.y += v.y; acc.z += v.z; acc.w += v.w;
    }
    float sc = 1.0f / fmaxf((float)(end - off), 1.0f);
    acc.x = rtf(acc.x * sc); acc.y = rtf(acc.y * sc);
    acc.z = rtf(acc.z * sc); acc.w = rtf(acc.w * sc);
    *((float4*)(out + (size_t)gw * DD) + lane) = acc;
}

// -------- embedding gather from bf16 tables --------
__global__ void embed_kernel(const int* __restrict__ uf,  const int* __restrict__ itf,
                             const int* __restrict__ ut,  const int* __restrict__ it) {
    int gw   = (blockIdx.x * blockDim.x + threadIdx.x) >> 5;
    int lane = threadIdx.x & 31;
    if (gw >= NNODE) return;
    int n = gw;
    bool user = n < NUSR;
    const int* f = user ? uf + (size_t)n * 10 : itf + (size_t)(n - NUSR) * 10;
    const __nv_bfloat16* tab = user ? g_ufeb : g_ifeb;

    float4 a = make_float4(0.f, 0.f, 0.f, 0.f);
#pragma unroll
    for (int j = 0; j < 10; j++) {
        int r = __ldg(f + j);
        uint2 v = __ldg((const uint2*)(tab + (size_t)r * DD) + lane);
        float2 p0 = __bfloat1622float2(*(__nv_bfloat162*)&v.x);
        float2 p1 = __bfloat1622float2(*(__nv_bfloat162*)&v.y);
        a.x += p0.x; a.y += p0.y; a.z += p1.x; a.w += p1.y;
    }
    float* catrow = g_cat + (size_t)n * KCAT;
    a.x = rtf(a.x * 0.1f); a.y = rtf(a.y * 0.1f);
    a.z = rtf(a.z * 0.1f); a.w = rtf(a.w * 0.1f);
    ((float4*)catrow)[lane] = a;

    const int* t = user ? ut + (size_t)n * 24 : it + (size_t)(n - NUSR) * 24;
#pragma unroll
    for (int fl = 0; fl < 3; fl++) {
        float2 b = make_float2(0.f, 0.f);
#pragma unroll
        for (int w = 0; w < 8; w++) {
            int r = __ldg(t + fl * 8 + w);
            uint32_t v = __ldg((const uint32_t*)(g_web + (size_t)r * HALFD) + lane);
            float2 p = __bfloat1622float2(*(__nv_bfloat162*)&v);
            b.x += p.x; b.y += p.y;
        }
        b.x = rtf(b.x * 0.125f); b.y = rtf(b.y * 0.125f);
        ((float2*)(catrow + 128 + fl * 64))[lane] = b;
    }
}

// ======== TF32 GEMM, W-as-A / nodes-as-B operand mapping ========
// out[node][col] = sum_k node[k] * W[k][col] (+bias +addmat), BK=32, A dist-1 / B dist-2
// dyn smem: SA[2][4224] (interleaved W) | SB[3][128][SBPAD32]
__global__ __launch_bounds__(256, 2) void gemm_tf32(
    const float* __restrict__ A,  int K1, int woff,
    const float* __restrict__ bias,
    const float* __restrict__ addmat,
    float* __restrict__ out, int M)
{
    extern __shared__ float sm_[];
    float* SA = sm_;
    float* SB = sm_ + 2 * 4224;
    const float* Wt = g_wts + woff;

    int tid  = threadIdx.x;
    int lane = tid & 31;
    int wid  = tid >> 5;
    int wm = wid & 1, wn = wid >> 1;
    int g  = lane >> 2, tg = lane & 3;
    int r0 = blockIdx.x * 128;

    float acc[4][4][4];
#pragma unroll
    for (int mt = 0; mt < 4; mt++)
#pragma unroll
        for (int nt = 0; nt < 4; nt++)
#pragma unroll
            for (int u = 0; u < 4; u++) acc[mt][nt][u] = 0.f;

    int T = K1 / 32;
    auto issueSA = [&](int t, int s) {
        float* dst = SA + s * 4224;
        const float* srcb = Wt + (size_t)t * 4224;
#pragma unroll
        for (int l = 0; l < 5; l++) {
            int idx = tid + l * 256;
            if (idx < 1056) cp16(dst + idx * 4, srcb + idx * 4, true);
        }
        cp_commit();
    };
    auto issueSB = [&](int t, int s) {
        float* dst = SB + s * 128 * SBPAD32;
#pragma unroll
        for (int l = 0; l < 4; l++) {
            int idx = tid + l * 256;
            int m = idx >> 3, c8 = (idx & 7) * 4;
            int row = r0 + m;
            cp16(dst + m * SBPAD32 + c8, A + (size_t)row * K1 + t * 32 + c8, row < M);
        }
        cp_commit();
    };

    issueSA(0, 0);
    issueSB(0, 0);
    issueSB(1, 1);
    for (int t = 0; t < T; t++) {
        int sa = t & 1, sb = t % 3;
        if (t + 1 < T) issueSA(t + 1, (t + 1) & 1);
        if (t + 2 < T) issueSB(t + 2, (t + 2) % 3);
        if (t + 2 < T) cp_wait3();
        else if (t + 1 < T) cp_wait2();
        else cp_wait0();
        __syncthreads();
        const float* SAs = SA + sa * 4224;
        const float* SBs = SB + sb * 128 * SBPAD32;
#pragma unroll
        for (int ks = 0; ks < 32; ks += 8) {
            const float2* ap = (const float2*)(SAs + (ks >> 3) * 1056 + tg * 264);
            uint32_t afr[4][4];
#pragma unroll
            for (int mt = 0; mt < 4; mt++) {
                int col = wm * 64 + mt * 16 + g;
                float2 f1 = ap[col], f2 = ap[col + 8];
                afr[mt][0] = __float_as_uint(f1.x);
                afr[mt][1] = __float_as_uint(f2.x);
                afr[mt][2] = __float_as_uint(f1.y);
                afr[mt][3] = __float_as_uint(f2.y);
            }
            uint32_t bfr[4][2];
#pragma unroll
            for (int nt = 0; nt < 4; nt++) {
                int nn = wn * 32 + nt * 8 + g;
                bfr[nt][0] = __float_as_uint(SBs[nn * SBPAD32 + ks + tg]);
                bfr[nt][1] = __float_as_uint(SBs[nn * SBPAD32 + ks + tg + 4]);
            }
#pragma unroll
            for (int mt = 0; mt < 4; mt++)
#pragma unroll
                for (int nt = 0; nt < 4; nt++)
                    mma_tf32(acc[mt][nt], afr[mt], bfr[nt]);
        }
        __syncthreads();
    }

#pragma unroll
    for (int mt = 0; mt < 4; mt++) {
        int colA = wm * 64 + mt * 16 + g, colB = colA + 8;
        float ba = bias[colA], bb = bias[colB];
#pragma unroll
        for (int nt = 0; nt < 4; nt++) {
            int nodeA = r0 + wn * 32 + nt * 8 + tg * 2;
            int nodeB = nodeA + 1;
            if (nodeA < M) {
                out[(size_t)nodeA * 128 + colA] = rtf(acc[mt][nt][0] + ba + addmat[(size_t)nodeA * 128 + colA]);
                out[(size_t)nodeA * 128 + colB] = rtf(acc[mt][nt][2] + bb + addmat[(size_t)nodeA * 128 + colB]);
            }
            if (nodeB < M) {
                out[(size_t)nodeB * 128 + colA] = rtf(acc[mt][nt][1] + ba + addmat[(size_t)nodeB * 128 + colA]);
                out[(size_t)nodeB * 128 + colB] = rtf(acc[mt][nt][3] + bb + addmat[(size_t)nodeB * 128 + colB]);
            }
        }
    }
}

// ======== fused SAGE layer, 24 tiles BK=16, same operand mapping ========
// tiles 0..7: h-GEMM (B=agg, A=vW) -> Hs; 8..15: B=x, A=wW[0:128]; 16..23: B=Hs, A=wW[128:256]
// dyn smem: SA[2][2112] | SB[3][128][SBPAD16] | Hs[128*128 swizzled]
template <bool RELU>
__global__ __launch_bounds__(256, 2) void sage_layer(
    const float* __restrict__ agg, const float* __restrict__ x,
    int voff, const float* __restrict__ vb,
    int woff, const float* __restrict__ wb,
    float* __restrict__ out, int M)
{
    extern __shared__ float sm_[];
    float* SA = sm_;
    float* SB = sm_ + 2 * 2112;
    float* Hs = sm_ + 2 * 2112 + 3 * 128 * SBPAD16;
    const float* vW = g_wts + voff;
    const float* wW = g_wts + woff;

    int tid  = threadIdx.x;
    int lane = tid & 31;
    int wid  = tid >> 5;
    int wm = wid & 1, wn = wid >> 1;
    int g  = lane >> 2, tg = lane & 3;
    int r0 = blockIdx.x * 128;

    float acc[4][4][4];
#pragma unroll
    for (int mt = 0; mt < 4; mt++)
#pragma unroll
        for (int nt = 0; nt < 4; nt++)
#pragma unroll
            for (int u = 0; u < 4; u++) acc[mt][nt][u] = 0.f;

    auto issueSA = [&](int wt, int s) {
        float* dst = SA + s * 2112;
        const float* srcb = (wt < 8) ? (vW + (size_t)wt * 2112)
                                     : (wW + (size_t)(wt - 8) * 2112);
#pragma unroll
        for (int l = 0; l < 3; l++) {
            int idx = tid + l * 256;
            if (idx < 528) cp16(dst + idx * 4, srcb + idx * 4, true);
        }
        cp_commit();
    };
    auto issueSB = [&](int at, int s) {
        const float* Ap = (at < 8) ? agg : x;
        int kt = (at < 8) ? at : at - 8;
        float* dst = SB + s * 128 * SBPAD16;
#pragma unroll
        for (int l = 0; l < 2; l++) {
            int idx = tid + l * 256;
            int m = idx >> 2, c4 = (idx & 3) * 4;
            int row = r0 + m;
            cp16(dst + m * SBPAD16 + c4, Ap + (size_t)row * DD + kt * 16 + c4, row < M);
        }
        cp_commit();
    };

    issueSA(0, 0);
    issueSB(0, 0);
    issueSB(1, 1);

    for (int t = 0; t < 24; t++) {
        int sa = t & 1, sb = t % 3;
        if (t + 1 < 24) issueSA(t + 1, (t + 1) & 1);
        if (t + 2 < 16) issueSB(t + 2, (t + 2) % 3);
        if (t < 14) cp_wait3();
        else if (t == 14) cp_wait2();
        else if (t < 23) cp_wait1();
        else cp_wait0();
        __syncthreads();

        const float* SAs = SA + sa * 2112;
        const float* SBs = SB + sb * 128 * SBPAD16;
        int hc = (t - 16) * 16;
#pragma unroll
        for (int ks = 0; ks < 16; ks += 8) {
            const float2* ap = (const float2*)(SAs + (ks >> 3) * 1056 + tg * 264);
            uint32_t afr[4][4];
#pragma unroll
            for (int mt = 0; mt < 4; mt++) {
                int col = wm * 64 + mt * 16 + g;
                float2 f1 = ap[col], f2 = ap[col + 8];
                afr[mt][0] = __float_as_uint(f1.x);
                afr[mt][1] = __float_as_uint(f2.x);
                afr[mt][2] = __float_as_uint(f1.y);
                afr[mt][3] = __float_as_uint(f2.y);
            }
            uint32_t bfr[4][2];
#pragma unroll
            for (int nt = 0; nt < 4; nt++) {
                int nn = wn * 32 + nt * 8 + g;
                if (t < 16) {
                    bfr[nt][0] = __float_as_uint(SBs[nn * SBPAD16 + ks + tg]);
                    bfr[nt][1] = __float_as_uint(SBs[nn * SBPAD16 + ks + tg + 4]);
                } else {
                    bfr[nt][0] = __float_as_uint(Hs[hsw(nn, hc + ks + tg)]);
                    bfr[nt][1] = __float_as_uint(Hs[hsw(nn, hc + ks + tg + 4)]);
                }
            }
#pragma unroll
            for (int mt = 0; mt < 4; mt++)
#pragma unroll
                for (int nt = 0; nt < 4; nt++)
                    mma_tf32(acc[mt][nt], afr[mt], bfr[nt]);
        }

        if (t == 7) {
            // h = relu(acc + vb) -> Hs (tf32), reset acc
#pragma unroll
            for (int mt = 0; mt < 4; mt++) {
                int colA = wm * 64 + mt * 16 + g, colB = colA + 8;
                float ba = vb[colA], bb = vb[colB];
#pragma unroll
                for (int nt = 0; nt < 4; nt++) {
                    int nA = wn * 32 + nt * 8 + tg * 2, nB = nA + 1;
                    Hs[hsw(nA, colA)] = rtf(fmaxf(acc[mt][nt][0] + ba, 0.f));
                    Hs[hsw(nB, colA)] = rtf(fmaxf(acc[mt][nt][1] + ba, 0.f));
                    Hs[hsw(nA, colB)] = rtf(fmaxf(acc[mt][nt][2] + bb, 0.f));
                    Hs[hsw(nB, colB)] = rtf(fmaxf(acc[mt][nt][3] + bb, 0.f));
#pragma unroll
                    for (int u = 0; u < 4; u++) acc[mt][nt][u] = 0.f;
                }
            }
        }
        __syncthreads();
    }

    // epilogue
#pragma unroll
    for (int mt = 0; mt < 4; mt++) {
        int colA = wm * 64 + mt * 16 + g, colB = colA + 8;
        float ba = wb[colA], bb = wb[colB];
#pragma unroll
        for (int nt = 0; nt < 4; nt++) {
            int nodeA = r0 + wn * 32 + nt * 8 + tg * 2;
            int nodeB = nodeA + 1;
            float v0 = acc[mt][nt][0] + ba, v1 = acc[mt][nt][1] + ba;
            float v2 = acc[mt][nt][2] + bb, v3 = acc[mt][nt][3] + bb;
            if (RELU) {
                v0 = rtf(fmaxf(v0, 0.f)); v1 = rtf(fmaxf(v1, 0.f));
                v2 = rtf(fmaxf(v2, 0.f)); v3 = rtf(fmaxf(v3, 0.f));
            }
            if (nodeA < M) {
                out[(size_t)nodeA * 128 + colA] = v0;
                out[(size_t)nodeA * 128 + colB] = v2;
            }
            if (nodeB < M) {
                out[(size_t)nodeB * 128 + colA] = v1;
                out[(size_t)nodeB * 128 + colB] = v3;
            }
        }
    }
}

// -------- launch --------
extern "C" void kernel_launch(void* const* d_in, const int* in_sizes, int n_in,
                              void* d_out, int out_size) {
    const int*   edge          = (const int*)d_in[0];
    const int*   src           = edge;
    const int*   dstp          = edge + EE;
    const int*   user_features = (const int*)d_in[1];
    const int*   item_features = (const int*)d_in[2];
    const int*   user_text     = (const int*)d_in[3];
    const int*   item_text     = (const int*)d_in[4];
    const float* user_id_emb   = (const float*)d_in[5];
    const float* item_id_emb   = (const float*)d_in[6];
    const float* user_feat_emb = (const float*)d_in[7];
    const float* item_feat_emb = (const float*)d_in[8];
    const float* word_emb      = (const float*)d_in[9];
    const float* user_projW    = (const float*)d_in[10];
    const float* user_projb    = (const float*)d_in[11];
    const float* item_projW    = (const float*)d_in[12];
    const float* item_projb    = (const float*)d_in[13];
    const float* w0W = (const float*)d_in[14];
    const float* w0b = (const float*)d_in[15];
    const float* w1W = (const float*)d_in[16];
    const float* w1b = (const float*)d_in[17];
    const float* v0W = (const float*)d_in[18];
    const float* v0b = (const float*)d_in[19];
    const float* v1W = (const float*)d_in[20];
    const float* v1b = (const float*)d_in[21];

    float *pA, *pB, *pcat;
    int   *pdeg;
    cudaGetSymbolAddress((void**)&pA,   g_bufA);
    cudaGetSymbolAddress((void**)&pB,   g_bufB);
    cudaGetSymbolAddress((void**)&pcat, g_cat);
    cudaGetSymbolAddress((void**)&pdeg, g_deg);

    const int GEMM_SMEM = (2 * 4224 + 3 * 128 * SBPAD32) * 4;              // 89088
    const int SAGE_SMEM = (2 * 2112 + 3 * 128 * SBPAD16 + 128 * 128) * 4;  // 113152
    cudaFuncSetAttribute(gemm_tf32, cudaFuncAttributeMaxDynamicSharedMemorySize, GEMM_SMEM);
    cudaFuncSetAttribute(sage_layer<true>,  cudaFuncAttributeMaxDynamicSharedMemorySize, SAGE_SMEM);
    cudaFuncSetAttribute(sage_layer<false>, cudaFuncAttributeMaxDynamicSharedMemorySize, SAGE_SMEM);

    // order: launch index 3 = user projection GEMM (profiler slot)
    roundw_kernel<<<(180224 + 255) / 256, 256>>>(user_projW, item_projW,     // 0
                                                 w0W, w1W, v0W, v1W);
    conv_tables<<<2048, 256>>>(user_feat_emb, item_feat_emb, word_emb);      // 1
    embed_kernel<<<(NNODE * 32 + 255) / 256, 256>>>(                         // 2
        user_features, item_features, user_text, item_text);
    gemm_tf32<<<(NUSR + 127) / 128, 256, GEMM_SMEM>>>(                       // 3 (profiled)
        pcat, KCAT, DOFF_U, user_projb, user_id_emb, pA, NUSR);
    gemm_tf32<<<(NITM + 127) / 128, 256, GEMM_SMEM>>>(                       // 4
        pcat + (size_t)NUSR * KCAT, KCAT, DOFF_I, item_projb, item_id_emb,
        pA + (size_t)NUSR * DD, NITM);
    zero_kernel<<<64, 256>>>((uint4*)pdeg, NNODE / 4);                       // 5
    deg_kernel<<<(EE + 255) / 256, 256>>>(dstp);                             // 6
    scan1_kernel<<<NBLK, 256>>>();                                           // 7
    scan2_kernel<<<1, 1024>>>();                                             // 8
    scan3_kernel<<<(NNODE + 255) / 256, 256>>>();                            // 9
    fill_kernel<<<(EE + 255) / 256, 256>>>(src, dstp);                       // 10

    // ----- layer 0 -----
    agg_kernel<<<(NNODE * 32 + 255) / 256, 256>>>(pA, pB);                   // 11
    sage_layer<true><<<(NNODE + 127) / 128, 256, SAGE_SMEM>>>(               // 12
        pB, pA, DOFF_V0, v0b, DOFF_W0, w0b, pcat, NNODE);

    // ----- layer 1 -----
    agg_kernel<<<(NNODE * 32 + 255) / 256, 256>>>(pcat, pA);                 // 13
    sage_layer<false><<<(NNODE + 127) / 128, 256, SAGE_SMEM>>>(              // 14
        pA, pcat, DOFF_V1, v1b, DOFF_W1, w1b, (float*)d_out, NNODE);
}

// round 8
// speedup vs baseline: 1.0290x; 1.0290x over previous
#include <cuda_runtime.h>
#include <cuda_bf16.h>
#include <cstdint>

#define NUSR 100000
#define NITM 50000
#define NNODE (NUSR + NITM)
#define DD 128
#define EE 1500000
#define HALFD 64
#define KCAT 320
#define NBLK 586   // ceil(NNODE/256)

#define APAD16 20
#define APAD32 36

// weight buffer offsets (floats), plain [k][128] row-major, tf32-rounded
#define OFF_U  0
#define OFF_I  40960
#define OFF_W0 81920
#define OFF_W1 114688
#define OFF_V0 147456
#define OFF_V1 163840
#define WTOT   180224

// -------- scratch (device globals: allocation-free) --------
__device__ float g_bufA[(size_t)NNODE * DD];
__device__ float g_bufB[(size_t)NNODE * DD];
__device__ float g_cat [(size_t)NNODE * KCAT];
__device__ float g_wts [WTOT];
__device__ int   g_deg[NNODE];
__device__ int   g_bsum[1024];
__device__ int   g_offs[NNODE + 1];
__device__ int   g_cursor[NNODE];
__device__ int   g_csr[EE];
__device__ __nv_bfloat16 g_ufeb[5000 * 128];
__device__ __nv_bfloat16 g_ifeb[8000 * 128];
__device__ __nv_bfloat16 g_web [30000 * 64];

// -------- tf32 helpers --------
__device__ __forceinline__ uint32_t f2tf32(float v) {
    uint32_t r;
    asm("cvt.rna.tf32.f32 %0, %1;" : "=r"(r) : "f"(v));
    return r;
}
__device__ __forceinline__ float rtf(float v) { return __uint_as_float(f2tf32(v)); }

__device__ __forceinline__ void mma_tf32(float* c, const uint32_t* a, const uint32_t* b) {
    asm volatile(
        "mma.sync.aligned.m16n8k8.row.col.f32.tf32.tf32.f32 "
        "{%0,%1,%2,%3}, {%4,%5,%6,%7}, {%8,%9}, {%0,%1,%2,%3};"
        : "+f"(c[0]), "+f"(c[1]), "+f"(c[2]), "+f"(c[3])
        : "r"(a[0]), "r"(a[1]), "r"(a[2]), "r"(a[3]), "r"(b[0]), "r"(b[1]));
}

__device__ __forceinline__ void cp16cg(void* smem_dst, const void* gsrc, bool pred) {
    uint32_t dst = (uint32_t)__cvta_generic_to_shared(smem_dst);
    int sz = pred ? 16 : 0;
    asm volatile("cp.async.cg.shared.global [%0], [%1], 16, %2;\n"
                 :: "r"(dst), "l"(gsrc), "r"(sz));
}
__device__ __forceinline__ void cp_commit() { asm volatile("cp.async.commit_group;\n"); }
__device__ __forceinline__ void cp_wait0()  { asm volatile("cp.async.wait_group 0;\n"); }
__device__ __forceinline__ void cp_wait1()  { asm volatile("cp.async.wait_group 1;\n"); }

// Hs swizzle: row-major [128][128], phys col = col ^ (4*(row&7))
__device__ __forceinline__ int hsw(int r, int c) { return r * 128 + (c ^ ((r & 7) << 2)); }

// -------- utility kernels --------
__global__ void zero_kernel(uint4* __restrict__ p, int n4) {
    int i = blockIdx.x * blockDim.x + threadIdx.x;
    int st = gridDim.x * blockDim.x;
    for (; i < n4; i += st) p[i] = make_uint4(0, 0, 0, 0);
}

// weights -> tf32-rounded, plain [k][128] layout
__global__ void roundw_kernel(const float* __restrict__ uW, const float* __restrict__ iW,
                              const float* __restrict__ w0, const float* __restrict__ w1,
                              const float* __restrict__ v0, const float* __restrict__ v1) {
    int i = blockIdx.x * blockDim.x + threadIdx.x;
    if (i >= WTOT) return;
    float v;
    if      (i < OFF_I)  v = uW[i - OFF_U];
    else if (i < OFF_W0) v = iW[i - OFF_I];
    else if (i < OFF_W1) v = w0[i - OFF_W0];
    else if (i < OFF_V0) v = w1[i - OFF_W1];
    else if (i < OFF_V1) v = v0[i - OFF_V0];
    else                 v = v1[i - OFF_V1];
    g_wts[i] = rtf(v);
}

// embedding tables -> bf16
__global__ void conv_tables(const float* __restrict__ ufe, const float* __restrict__ ife,
                            const float* __restrict__ we) {
    int i = blockIdx.x * blockDim.x + threadIdx.x;
    int st = gridDim.x * blockDim.x;
    for (; i < 3584000; i += st) {
        if      (i < 640000)  g_ufeb[i]           = __float2bfloat16(ufe[i]);
        else if (i < 1664000) g_ifeb[i - 640000]  = __float2bfloat16(ife[i - 640000]);
        else                  g_web [i - 1664000] = __float2bfloat16(we [i - 1664000]);
    }
}

__global__ void deg_kernel(const int* __restrict__ dst) {
    int i = blockIdx.x * blockDim.x + threadIdx.x;
    if (i < EE) atomicAdd(&g_deg[dst[i]], 1);
}

__global__ void scan1_kernel() {
    __shared__ int sm[256];
    int tid = threadIdx.x;
    int i = blockIdx.x * 256 + tid;
    int v = (i < NNODE) ? g_deg[i] : 0;
    sm[tid] = v;
    __syncthreads();
#pragma unroll
    for (int d = 1; d < 256; d <<= 1) {
        int t = (tid >= d) ? sm[tid - d] : 0;
        __syncthreads();
        sm[tid] += t;
        __syncthreads();
    }
    if (i < NNODE) g_offs[i] = sm[tid] - v;
    if (tid == 255) g_bsum[blockIdx.x] = sm[255];
}

__global__ void scan2_kernel() {
    __shared__ int sm[1024];
    int tid = threadIdx.x;
    int v = (tid < NBLK) ? g_bsum[tid] : 0;
    sm[tid] = v;
    __syncthreads();
#pragma unroll
    for (int d = 1; d < 1024; d <<= 1) {
        int t = (tid >= d) ? sm[tid - d] : 0;
        __syncthreads();
        sm[tid] += t;
        __syncthreads();
    }
    g_bsum[tid] = sm[tid] - v;
}

__global__ void scan3_kernel() {
    int i = blockIdx.x * blockDim.x + threadIdx.x;
    if (i < NNODE) {
        int o = g_offs[i] + g_bsum[i >> 8];
        g_offs[i] = o;
        g_cursor[i] = o;
    }
    if (i == 0) g_offs[NNODE] = EE;
}

__global__ void fill_kernel(const int* __restrict__ src, const int* __restrict__ dst) {
    int i = blockIdx.x * blockDim.x + threadIdx.x;
    if (i < EE) {
        int d = dst[i];
        int pos = atomicAdd(&g_cursor[d], 1);
        g_csr[pos] = src[i];
    }
}

// -------- gather aggregation (warp per node), invdeg from CSR offsets --------
__global__ void agg_kernel(const float* __restrict__ x, float* __restrict__ out) {
    int gw   = (blockIdx.x * blockDim.x + threadIdx.x) >> 5;
    int lane = threadIdx.x & 31;
    if (gw >= NNODE) return;
    int off = g_offs[gw];
    int end = g_offs[gw + 1];
    float4 acc = make_float4(0.f, 0.f, 0.f, 0.f);
    for (int j = off; j < end; j++) {
        int s = __ldg(&g_csr[j]);
        float4 v = __ldg((const float4*)(x + (size_t)s * DD) + lane);
        acc.x += v.x; acc.y += v.y; acc.z += v.z; acc.w += v.w;
    }
    float sc = 1.0f / fmaxf((float)(end - off), 1.0f);
    acc.x = rtf(acc.x * sc); acc.y = rtf(acc.y * sc);
    acc.z = rtf(acc.z * sc); acc.w = rtf(acc.w * sc);
    *((float4*)(out + (size_t)gw * DD) + lane) = acc;
}

// -------- embedding gather from bf16 tables --------
__global__ void embed_kernel(const int* __restrict__ uf,  const int* __restrict__ itf,
                             const int* __restrict__ ut,  const int* __restrict__ it) {
    int gw   = (blockIdx.x * blockDim.x + threadIdx.x) >> 5;
    int lane = threadIdx.x & 31;
    if (gw >= NNODE) return;
    int n = gw;
    bool user = n < NUSR;
    const int* f = user ? uf + (size_t)n * 10 : itf + (size_t)(n - NUSR) * 10;
    const __nv_bfloat16* tab = user ? g_ufeb : g_ifeb;

    float4 a = make_float4(0.f, 0.f, 0.f, 0.f);
#pragma unroll
    for (int j = 0; j < 10; j++) {
        int r = __ldg(f + j);
        uint2 v = __ldg((const uint2*)(tab + (size_t)r * DD) + lane);
        float2 p0 = __bfloat1622float2(*(__nv_bfloat162*)&v.x);
        float2 p1 = __bfloat1622float2(*(__nv_bfloat162*)&v.y);
        a.x += p0.x; a.y += p0.y; a.z += p1.x; a.w += p1.y;
    }
    float* catrow = g_cat + (size_t)n * KCAT;
    a.x = rtf(a.x * 0.1f); a.y = rtf(a.y * 0.1f);
    a.z = rtf(a.z * 0.1f); a.w = rtf(a.w * 0.1f);
    ((float4*)catrow)[lane] = a;

    const int* t = user ? ut + (size_t)n * 24 : it + (size_t)(n - NUSR) * 24;
#pragma unroll
    for (int fl = 0; fl < 3; fl++) {
        float2 b = make_float2(0.f, 0.f);
#pragma unroll
        for (int w = 0; w < 8; w++) {
            int r = __ldg(t + fl * 8 + w);
            uint32_t v = __ldg((const uint32_t*)(g_web + (size_t)r * HALFD) + lane);
            float2 p = __bfloat1622float2(*(__nv_bfloat162*)&v);
            b.x += p.x; b.y += p.y;
        }
        b.x = rtf(b.x * 0.125f); b.y = rtf(b.y * 0.125f);
        ((float2*)(catrow + 128 + fl * 64))[lane] = b;
    }
}

// ======== TF32 GEMM (projection): nodes via cp.async 3-stage, weights via __ldg ========
// out[M,128] = A[M,K1] @ Wt[K1,128] + bias + addmat   (output tf32-rounded)
// dyn smem: As[3][128][APAD32]  — single __syncthreads per K-tile
__global__ __launch_bounds__(256) void gemm_tf32(
    const float* __restrict__ A,  int K1, int woff,
    const float* __restrict__ bias,
    const float* __restrict__ addmat,
    float* __restrict__ out, int M)
{
    extern __shared__ float sm_[];
    float (*As)[128][APAD32] = (float (*)[128][APAD32])sm_;
    const float* Wt = g_wts + woff;

    int tid  = threadIdx.x;
    int lane = tid & 31;
    int wid  = tid >> 5;
    int wm = wid & 1, wn = wid >> 1;
    int g  = lane >> 2, tg = lane & 3;
    int r0 = blockIdx.x * 128;

    float acc[4][4][4];
#pragma unroll
    for (int mt = 0; mt < 4; mt++)
#pragma unroll
        for (int nt = 0; nt < 4; nt++)
#pragma unroll
            for (int u = 0; u < 4; u++) acc[mt][nt][u] = 0.f;

    int T = K1 / 32;
    auto issue = [&](int t, int s) {
#pragma unroll
        for (int l = 0; l < 4; l++) {
            int idx = tid + l * 256;
            int m = idx >> 3, c8 = (idx & 7) * 4;
            int row = r0 + m;
            cp16cg(&As[s][m][c8], A + (size_t)row * K1 + t * 32 + c8, row < M);
        }
        cp_commit();
    };

    issue(0, 0);
    issue(1, 1);
    for (int t = 0; t < T; t++) {
        int sa = t % 3;
        if (t + 1 < T) cp_wait1(); else cp_wait0();
        __syncthreads();
#pragma unroll
        for (int ks = 0; ks < 32; ks += 8) {
            int krow = t * 32 + ks + tg;
            uint32_t afr[4][4];
#pragma unroll
            for (int mt = 0; mt < 4; mt++) {
                int rb = wm * 64 + mt * 16 + g;
                afr[mt][0] = __float_as_uint(As[sa][rb    ][ks + tg]);
                afr[mt][1] = __float_as_uint(As[sa][rb + 8][ks + tg]);
                afr[mt][2] = __float_as_uint(As[sa][rb    ][ks + tg + 4]);
                afr[mt][3] = __float_as_uint(As[sa][rb + 8][ks + tg + 4]);
            }
            uint32_t bfr[4][2];
#pragma unroll
            for (int nt = 0; nt < 4; nt++) {
                int cb = wn * 32 + nt * 8 + g;
                bfr[nt][0] = __float_as_uint(__ldg(Wt + (size_t)krow * 128 + cb));
                bfr[nt][1] = __float_as_uint(__ldg(Wt + (size_t)(krow + 4) * 128 + cb));
            }
#pragma unroll
            for (int mt = 0; mt < 4; mt++)
#pragma unroll
                for (int nt = 0; nt < 4; nt++)
                    mma_tf32(acc[mt][nt], afr[mt], bfr[nt]);
        }
        if (t + 2 < T) issue(t + 2, (t + 2) % 3);
    }

#pragma unroll
    for (int mt = 0; mt < 4; mt++) {
#pragma unroll
        for (int nt = 0; nt < 4; nt++) {
            int col = wn * 32 + nt * 8 + tg * 2;
            int rowa = r0 + wm * 64 + mt * 16 + g;
            int rowb = rowa + 8;
            float b0 = bias[col], b1 = bias[col + 1];
            if (rowa < M) {
                float x0 = rtf(acc[mt][nt][0] + b0 + addmat[(size_t)rowa * 128 + col]);
                float x1 = rtf(acc[mt][nt][1] + b1 + addmat[(size_t)rowa * 128 + col + 1]);
                *(float2*)(out + (size_t)rowa * 128 + col) = make_float2(x0, x1);
            }
            if (rowb < M) {
                float x2 = rtf(acc[mt][nt][2] + b0 + addmat[(size_t)rowb * 128 + col]);
                float x3 = rtf(acc[mt][nt][3] + b1 + addmat[(size_t)rowb * 128 + col + 1]);
                *(float2*)(out + (size_t)rowb * 128 + col) = make_float2(x2, x3);
            }
        }
    }
}

// ======== fused SAGE layer: 24 tiles BK=16, nodes cp.async 3-stage, weights __ldg ========
// tiles 0..7: h = agg@vW; 8..15: x@wW[0:128]; 16..23: Hs@wW[128:256]
// dyn smem: As[3][128][APAD16] | Hs[128*128 swizzled]
template <bool RELU>
__global__ __launch_bounds__(256) void sage_layer(
    const float* __restrict__ agg, const float* __restrict__ x,
    int voff, const float* __restrict__ vb,
    int woff, const float* __restrict__ wb,
    float* __restrict__ out, int M)
{
    extern __shared__ float sm_[];
    float (*As)[128][APAD16] = (float (*)[128][APAD16])sm_;
    float* Hs = sm_ + 3 * 128 * APAD16;
    const float* vW = g_wts + voff;
    const float* wW = g_wts + woff;

    int tid  = threadIdx.x;
    int lane = tid & 31;
    int wid  = tid >> 5;
    int wm = wid & 1, wn = wid >> 1;
    int g  = lane >> 2, tg = lane & 3;
    int r0 = blockIdx.x * 128;

    float acc[4][4][4];
#pragma unroll
    for (int mt = 0; mt < 4; mt++)
#pragma unroll
        for (int nt = 0; nt < 4; nt++)
#pragma unroll
            for (int u = 0; u < 4; u++) acc[mt][nt][u] = 0.f;

    auto issue = [&](int at, int s) {
        const float* Ap = (at < 8) ? agg : x;
        int kt = (at < 8) ? at : at - 8;
#pragma unroll
        for (int l = 0; l < 2; l++) {
            int idx = tid + l * 256;
            int m = idx >> 2, c4 = (idx & 3) * 4;
            int row = r0 + m;
            cp16cg(&As[s][m][c4], Ap + (size_t)row * DD + kt * 16 + c4, row < M);
        }
        cp_commit();
    };

    issue(0, 0);
    issue(1, 1);

    for (int t = 0; t < 24; t++) {
        int sa = t % 3;
        if (t < 15) { cp_wait1(); __syncthreads(); }
        else if (t == 15) { cp_wait0(); __syncthreads(); }
        // t >= 16: reads Hs only (finalized before sync at t=8); no barrier needed

        const float* Wb = (t < 8) ? vW : wW;
        int kbase = (t < 8) ? t * 16 : (t - 8) * 16;
        int hc = (t - 16) * 16;
#pragma unroll
        for (int ks = 0; ks < 16; ks += 8) {
            int krow = kbase + ks + tg;
            uint32_t afr[4][4];
#pragma unroll
            for (int mt = 0; mt < 4; mt++) {
                int rb = wm * 64 + mt * 16 + g;
                if (t < 16) {
                    afr[mt][0] = __float_as_uint(As[sa][rb    ][ks + tg]);
                    afr[mt][1] = __float_as_uint(As[sa][rb + 8][ks + tg]);
                    afr[mt][2] = __float_as_uint(As[sa][rb    ][ks + tg + 4]);
                    afr[mt][3] = __float_as_uint(As[sa][rb + 8][ks + tg + 4]);
                } else {
                    afr[mt][0] = __float_as_uint(Hs[hsw(rb,     hc + ks + tg)]);
                    afr[mt][1] = __float_as_uint(Hs[hsw(rb + 8, hc + ks + tg)]);
                    afr[mt][2] = __float_as_uint(Hs[hsw(rb,     hc + ks + tg + 4)]);
                    afr[mt][3] = __float_as_uint(Hs[hsw(rb + 8, hc + ks + tg + 4)]);
                }
            }
            uint32_t bfr[4][2];
#pragma unroll
            for (int nt = 0; nt < 4; nt++) {
                int cb = wn * 32 + nt * 8 + g;
                bfr[nt][0] = __float_as_uint(__ldg(Wb + (size_t)krow * 128 + cb));
                bfr[nt][1] = __float_as_uint(__ldg(Wb + (size_t)(krow + 4) * 128 + cb));
            }
#pragma unroll
            for (int mt = 0; mt < 4; mt++)
#pragma unroll
                for (int nt = 0; nt < 4; nt++)
                    mma_tf32(acc[mt][nt], afr[mt], bfr[nt]);
        }

        if (t == 7) {
            // h = relu(acc + vb) -> Hs (tf32), reset acc  (ordered by sync at t=8)
#pragma unroll
            for (int mt = 0; mt < 4; mt++) {
#pragma unroll
                for (int nt = 0; nt < 4; nt++) {
                    int col = wn * 32 + nt * 8 + tg * 2;
                    int ra = wm * 64 + mt * 16 + g;
                    float b0 = vb[col], b1 = vb[col + 1];
                    Hs[hsw(ra,     col    )] = rtf(fmaxf(acc[mt][nt][0] + b0, 0.f));
                    Hs[hsw(ra,     col + 1)] = rtf(fmaxf(acc[mt][nt][1] + b1, 0.f));
                    Hs[hsw(ra + 8, col    )] = rtf(fmaxf(acc[mt][nt][2] + b0, 0.f));
                    Hs[hsw(ra + 8, col + 1)] = rtf(fmaxf(acc[mt][nt][3] + b1, 0.f));
#pragma unroll
                    for (int u = 0; u < 4; u++) acc[mt][nt][u] = 0.f;
                }
            }
        }
        if (t + 2 < 16) issue(t + 2, (t + 2) % 3);
    }

    // epilogue
#pragma unroll
    for (int mt = 0; mt < 4; mt++) {
#pragma unroll
        for (int nt = 0; nt < 4; nt++) {
            int col = wn * 32 + nt * 8 + tg * 2;
            int rowa = r0 + wm * 64 + mt * 16 + g;
            int rowb = rowa + 8;
            float b0 = wb[col], b1 = wb[col + 1];
            if (rowa < M) {
                float x0 = acc[mt][nt][0] + b0;
                float x1 = acc[mt][nt][1] + b1;
                if (RELU) { x0 = rtf(fmaxf(x0, 0.f)); x1 = rtf(fmaxf(x1, 0.f)); }
                *(float2*)(out + (size_t)rowa * 128 + col) = make_float2(x0, x1);
            }
            if (rowb < M) {
                float x2 = acc[mt][nt][2] + b0;
                float x3 = acc[mt][nt][3] + b1;
                if (RELU) { x2 = rtf(fmaxf(x2, 0.f)); x3 = rtf(fmaxf(x3, 0.f)); }
                *(float2*)(out + (size_t)rowb * 128 + col) = make_float2(x2, x3);
            }
        }
    }
}

// -------- launch --------
extern "C" void kernel_launch(void* const* d_in, const int* in_sizes, int n_in,
                              void* d_out, int out_size) {
    const int*   edge          = (const int*)d_in[0];
    const int*   src           = edge;
    const int*   dstp          = edge + EE;
    const int*   user_features = (const int*)d_in[1];
    const int*   item_features = (const int*)d_in[2];
    const int*   user_text     = (const int*)d_in[3];
    const int*   item_text     = (const int*)d_in[4];
    const float* user_id_emb   = (const float*)d_in[5];
    const float* item_id_emb   = (const float*)d_in[6];
    const float* user_feat_emb = (const float*)d_in[7];
    const float* item_feat_emb = (const float*)d_in[8];
    const float* word_emb      = (const float*)d_in[9];
    const float* user_projW    = (const float*)d_in[10];
    const float* user_projb    = (const float*)d_in[11];
    const float* item_projW    = (const float*)d_in[12];
    const float* item_projb    = (const float*)d_in[13];
    const float* w0W = (const float*)d_in[14];
    const float* w0b = (const float*)d_in[15];
    const float* w1W = (const float*)d_in[16];
    const float* w1b = (const float*)d_in[17];
    const float* v0W = (const float*)d_in[18];
    const float* v0b = (const float*)d_in[19];
    const float* v1W = (const float*)d_in[20];
    const float* v1b = (const float*)d_in[21];

    float *pA, *pB, *pcat;
    int   *pdeg;
    cudaGetSymbolAddress((void**)&pA,   g_bufA);
    cudaGetSymbolAddress((void**)&pB,   g_bufB);
    cudaGetSymbolAddress((void**)&pcat, g_cat);
    cudaGetSymbolAddress((void**)&pdeg, g_deg);

    const int GEMM_SMEM = (3 * 128 * APAD32) * 4;               // 55296
    const int SAGE_SMEM = (3 * 128 * APAD16 + 128 * 128) * 4;   // 96256
    cudaFuncSetAttribute(gemm_tf32, cudaFuncAttributeMaxDynamicSharedMemorySize, GEMM_SMEM);
    cudaFuncSetAttribute(sage_layer<true>,  cudaFuncAttributeMaxDynamicSharedMemorySize, SAGE_SMEM);
    cudaFuncSetAttribute(sage_layer<false>, cudaFuncAttributeMaxDynamicSharedMemorySize, SAGE_SMEM);

    // order: launch index 3 = user projection GEMM (profiler slot)
    roundw_kernel<<<(WTOT + 255) / 256, 256>>>(user_projW, item_projW,       // 0
                                               w0W, w1W, v0W, v1W);
    conv_tables<<<2048, 256>>>(user_feat_emb, item_feat_emb, word_emb);      // 1
    embed_kernel<<<(NNODE * 32 + 255) / 256, 256>>>(                         // 2
        user_features, item_features, user_text, item_text);
    gemm_tf32<<<(NUSR + 127) / 128, 256, GEMM_SMEM>>>(                       // 3 (profiled)
        pcat, KCAT, OFF_U, user_projb, user_id_emb, pA, NUSR);
    gemm_tf32<<<(NITM + 127) / 128, 256, GEMM_SMEM>>>(                       // 4
        pcat + (size_t)NUSR * KCAT, KCAT, OFF_I, item_projb, item_id_emb,
        pA + (size_t)NUSR * DD, NITM);
    zero_kernel<<<64, 256>>>((uint4*)pdeg, NNODE / 4);                       // 5
    deg_kernel<<<(EE + 255) / 256, 256>>>(dstp);                             // 6
    scan1_kernel<<<NBLK, 256>>>();                                           // 7
    scan2_kernel<<<1, 1024>>>();                                             // 8
    scan3_kernel<<<(NNODE + 255) / 256, 256>>>();                            // 9
    fill_kernel<<<(EE + 255) / 256, 256>>>(src, dstp);                       // 10

    // ----- layer 0 -----
    agg_kernel<<<(NNODE * 32 + 255) / 256, 256>>>(pA, pB);                   // 11
    sage_layer<true><<<(NNODE + 127) / 128, 256, SAGE_SMEM>>>(               // 12
        pB, pA, OFF_V0, v0b, OFF_W0, w0b, pcat, NNODE);

    // ----- layer 1 -----
    agg_kernel<<<(NNODE * 32 + 255) / 256, 256>>>(pcat, pA);                 // 13
    sage_layer<false><<<(NNODE + 127) / 128, 256, SAGE_SMEM>>>(              // 14
        pA, pcat, OFF_V1, v1b, OFF_W1, w1b, (float*)d_out, NNODE);
}